// round 1
// baseline (speedup 1.0000x reference)
#include <cuda_runtime.h>
#include <cuda_bf16.h>
#include <cstdint>

// QuantizedLinear: out[n][o] = sum_i x[n][i] * W[o][i] + bias[o]
//   W[o][i] = (nibble(w_packed[o][i/2], i&1) - 8) * w_scales[o]
//   low nibble -> even i, high nibble -> odd i
//
// Baseline: 128x128x16 SIMT fp32 tiled GEMM, 256 threads, 8x8 per-thread tile.
// Dequant fused into the W shared-memory fill.

#define BM 128
#define BN 128
#define BK 16
#define TM 8
#define TN 8
#define NTHREADS 256

__global__ __launch_bounds__(NTHREADS, 2)
void qlinear_kernel(const float* __restrict__ x,
                    const int*   __restrict__ wp,
                    const float* __restrict__ ws,
                    const float* __restrict__ bias,
                    float*       __restrict__ out,
                    int Nrows, int IN, int OUT)
{
    __shared__ float Xs[BK][BM + 4];   // Xs[k][n]
    __shared__ float Ws[BK][BN + 4];   // Ws[k][o]

    const int tid = threadIdx.x;
    const int tx  = tid & 15;          // 16 threads across o
    const int ty  = tid >> 4;          // 16 threads across n
    const int nBase = blockIdx.y * BM;
    const int oBase = blockIdx.x * BN;
    const int KP = IN >> 1;            // packed width (int32 per o-row)

    float acc[TM][TN];
    #pragma unroll
    for (int i = 0; i < TM; i++)
        #pragma unroll
        for (int j = 0; j < TN; j++)
            acc[i][j] = 0.0f;

    for (int k0 = 0; k0 < IN; k0 += BK) {
        // ---- load X tile: 128 rows x 16 cols = 512 float4, 2 per thread ----
        #pragma unroll
        for (int i = 0; i < 2; i++) {
            int idx  = tid + i * NTHREADS;       // 0..511
            int row  = idx >> 2;                 // 4 float4 per row
            int col4 = (idx & 3) << 2;
            float4 v = *(const float4*)(x + (size_t)(nBase + row) * IN + k0 + col4);
            Xs[col4 + 0][row] = v.x;
            Xs[col4 + 1][row] = v.y;
            Xs[col4 + 2][row] = v.z;
            Xs[col4 + 3][row] = v.w;
        }

        // ---- load + dequant W tile: 128 o-rows x 8 int32 = 1024, 4 per thread ----
        #pragma unroll
        for (int i = 0; i < 4; i++) {
            int idx  = tid + i * NTHREADS;       // 0..1023
            int orow = idx >> 3;                 // 8 int32 per o-row tile slice
            int kc   = idx & 7;                  // which packed int32 (2 k each)
            int packed = wp[(size_t)(oBase + orow) * KP + (k0 >> 1) + kc];
            float scale = ws[oBase + orow];
            float lo = (float)((packed      ) & 0xF) - 8.0f;
            float hi = (float)((packed >> 4) & 0xF) - 8.0f;
            Ws[kc * 2 + 0][orow] = lo * scale;
            Ws[kc * 2 + 1][orow] = hi * scale;
        }

        __syncthreads();

        // ---- 8x8 micro-tile FMA over BK ----
        #pragma unroll
        for (int k = 0; k < BK; k++) {
            float a[TM], b[TN];
            #pragma unroll
            for (int i = 0; i < TM; i++) a[i] = Xs[k][ty * TM + i];
            #pragma unroll
            for (int j = 0; j < TN; j++) b[j] = Ws[k][tx * TN + j];
            #pragma unroll
            for (int i = 0; i < TM; i++)
                #pragma unroll
                for (int j = 0; j < TN; j++)
                    acc[i][j] = fmaf(a[i], b[j], acc[i][j]);
        }

        __syncthreads();
    }

    // ---- epilogue: add bias, vectorized store ----
    const int oCol = oBase + tx * TN;
    float4 bvec0 = *(const float4*)(bias + oCol);
    float4 bvec1 = *(const float4*)(bias + oCol + 4);
    #pragma unroll
    for (int i = 0; i < TM; i++) {
        int n = nBase + ty * TM + i;
        float4 r0, r1;
        r0.x = acc[i][0] + bvec0.x;
        r0.y = acc[i][1] + bvec0.y;
        r0.z = acc[i][2] + bvec0.z;
        r0.w = acc[i][3] + bvec0.w;
        r1.x = acc[i][4] + bvec1.x;
        r1.y = acc[i][5] + bvec1.y;
        r1.z = acc[i][6] + bvec1.z;
        r1.w = acc[i][7] + bvec1.w;
        *(float4*)(out + (size_t)n * /*OUT*/ gridDim.x * BN + oCol)     = r0;
        *(float4*)(out + (size_t)n * gridDim.x * BN + oCol + 4)         = r1;
    }
}

extern "C" void kernel_launch(void* const* d_in, const int* in_sizes, int n_in,
                              void* d_out, int out_size)
{
    const float* x    = (const float*)d_in[0];
    const int*   wp   = (const int*)  d_in[1];
    const float* ws   = (const float*)d_in[2];
    const float* bias = (const float*)d_in[3];
    float*       out  = (float*)d_out;

    const int OUT   = in_sizes[2];                 // 4096
    const int IN    = (in_sizes[1] / OUT) * 2;     // 4096
    const int Nrows = in_sizes[0] / IN;            // 4096

    dim3 block(NTHREADS);
    dim3 grid(OUT / BN, Nrows / BM);
    qlinear_kernel<<<grid, block>>>(x, wp, ws, bias, out, Nrows, IN, OUT);
}

// round 5
// speedup vs baseline: 2.3444x; 2.3444x over previous
#include <cuda_runtime.h>
#include <cuda_bf16.h>
#include <cstdint>
#include <cstring>

// QuantizedLinear via mma.sync (HMMA) bf16 split-precision GEMM (base ISA,
// works with .target sm_103 — tcgen05 is arch-specific and rejected here).
//
// out[n][o] = (sum_i x[n][i] * (nib(o,i) - 8)) * scale[o] + bias[o]
// x = x_hi + x_lo (two bf16 MMAs), W nibbles exact in bf16.

#define NTHREADS 256
#define BM 128
#define BN 128
#define BK 64
#define IN_DIM 4096
#define OUT_DIM 4096
#define KP_DIM (IN_DIM / 2)         // int32 words per W row (2 k-values each)
#define NITER (IN_DIM / BK)         // 64

// smem: padded rows, 72 bf16 = 144 bytes per row (conflict-free for ldmatrix/STS)
#define ROWB 144
#define TILE_BYTES (128 * ROWB)     // 18432
#define A_HI_OFF 0
#define A_LO_OFF TILE_BYTES
#define B_OFF    (2 * TILE_BYTES)
#define STAGE_BYTES (3 * TILE_BYTES)          // 55296
#define OFF_SCALE (2 * STAGE_BYTES)           // 110592
#define OFF_BIAS  (OFF_SCALE + 512)
#define SMEM_TOTAL (OFF_BIAS + 512)

static __device__ __forceinline__ uint32_t smem_u32(const void* p) {
    uint32_t a;
    asm("{ .reg .u64 t; cvta.to.shared.u64 t, %1; cvt.u32.u64 %0, t; }" : "=r"(a) : "l"(p));
    return a;
}

static __device__ __forceinline__ void ldsm_x4(uint32_t& r0, uint32_t& r1,
                                               uint32_t& r2, uint32_t& r3, uint32_t addr) {
    asm volatile("ldmatrix.sync.aligned.m8n8.x4.shared.b16 {%0,%1,%2,%3}, [%4];"
                 : "=r"(r0), "=r"(r1), "=r"(r2), "=r"(r3) : "r"(addr));
}

static __device__ __forceinline__ void mma_bf16(float& c0, float& c1, float& c2, float& c3,
                                                uint32_t a0, uint32_t a1, uint32_t a2, uint32_t a3,
                                                uint32_t b0, uint32_t b1) {
    asm volatile("mma.sync.aligned.m16n8k16.row.col.f32.bf16.bf16.f32 "
                 "{%0,%1,%2,%3}, {%4,%5,%6,%7}, {%8,%9}, {%0,%1,%2,%3};"
                 : "+f"(c0), "+f"(c1), "+f"(c2), "+f"(c3)
                 : "r"(a0), "r"(a1), "r"(a2), "r"(a3), "r"(b0), "r"(b1));
}

static __device__ __forceinline__ uint32_t pack_bf2(float a, float b) {
    __nv_bfloat162 h = __floats2bfloat162_rn(a, b);
    uint32_t u; memcpy(&u, &h, 4); return u;
}

// one packed byte (int32) -> bf16x2: low nibble (even k) in low half
static __device__ __forceinline__ uint32_t dq(int p) {
    float lo = (float)((p & 0xF) - 8);
    float hi = (float)(((p >> 4) & 0xF) - 8);
    return pack_bf2(lo, hi);
}

__global__ __launch_bounds__(NTHREADS, 1)
void qlinear_mma(const float* __restrict__ x,
                 const int*   __restrict__ wp,
                 const float* __restrict__ ws,
                 const float* __restrict__ bias,
                 float*       __restrict__ out)
{
    extern __shared__ char smem[];
    const uint32_t sbase = smem_u32(smem);
    const int tid  = threadIdx.x;
    const int wid  = tid >> 5;
    const int lane = tid & 31;
    const int nBase = blockIdx.y * BM;     // x-row block
    const int oBase = blockIdx.x * BN;     // out-col block

    // warp tiling: 2 (M) x 4 (N); warp tile 64 x 32
    const int mWarp = (wid >> 2) * 64;
    const int nWarp = (wid & 3) * 32;

    // scale/bias to smem
    if (tid < 128) {
        *(float*)(smem + OFF_SCALE + tid * 4) = ws[oBase + tid];
        *(float*)(smem + OFF_BIAS  + tid * 4) = bias[oBase + tid];
    }

    // ---- loader geometry: row = tid>>1 (0..127), half th = tid&1 (32 k each) ----
    const int lrow = tid >> 1;
    const int th   = tid & 1;
    const float4* xg = (const float4*)x;
    const int4*   wg = (const int4*)wp;
    const size_t xRow = (size_t)(nBase + lrow) * (IN_DIM / 4);
    const size_t wRow = (size_t)(oBase + lrow) * (KP_DIM / 4);

    float4 fx[8];
    int4   fw[4];

    // ---- ldmatrix geometry ----
    const int lr = lane & 15;
    const int lc = lane >> 4;              // k-half (bytes +16)
    const uint32_t aRowOff = (uint32_t)(mWarp + lr) * ROWB + (uint32_t)lc * 16;
    const uint32_t bRowOff = (uint32_t)(nWarp + lr) * ROWB + (uint32_t)lc * 16;

    float acc[4][4][4];
    #pragma unroll
    for (int mt = 0; mt < 4; mt++)
        #pragma unroll
        for (int nt = 0; nt < 4; nt++)
            #pragma unroll
            for (int f = 0; f < 4; f++) acc[mt][nt][f] = 0.0f;

    // ---- tile load / convert helpers (macros keep everything in regs) ----
    #define LDG_TILE(it) do {                                                        \
        const int kc4 = (it) * (BK / 4) + th * 8;                                    \
        _Pragma("unroll")                                                            \
        for (int j = 0; j < 8; j++) fx[j] = __ldg(&xg[xRow + kc4 + j]);              \
        const int wc4 = (it) * (BK / 8) + th * 4;                                    \
        _Pragma("unroll")                                                            \
        for (int q = 0; q < 4; q++) fw[q] = __ldg(&wg[wRow + wc4 + q]);              \
    } while (0)

    #define STS_TILE(buf) do {                                                       \
        char* sb = smem + (size_t)(buf) * STAGE_BYTES;                               \
        const uint32_t base = (uint32_t)lrow * ROWB + (uint32_t)th * 64;             \
        uint32_t hi[16], lo[16];                                                     \
        _Pragma("unroll")                                                            \
        for (int j = 0; j < 8; j++) {                                                \
            float4 v = fx[j];                                                        \
            uint32_t h0 = pack_bf2(v.x, v.y);                                        \
            uint32_t h1 = pack_bf2(v.z, v.w);                                        \
            __nv_bfloat162 hh0, hh1;                                                 \
            memcpy(&hh0, &h0, 4); memcpy(&hh1, &h1, 4);                              \
            hi[j*2]   = h0; hi[j*2+1] = h1;                                          \
            lo[j*2]   = pack_bf2(v.x - __bfloat162float(hh0.x),                      \
                                 v.y - __bfloat162float(hh0.y));                     \
            lo[j*2+1] = pack_bf2(v.z - __bfloat162float(hh1.x),                      \
                                 v.w - __bfloat162float(hh1.y));                     \
        }                                                                            \
        _Pragma("unroll")                                                            \
        for (int q = 0; q < 4; q++) {                                                \
            *(uint4*)(sb + A_HI_OFF + base + q*16) =                                 \
                make_uint4(hi[q*4], hi[q*4+1], hi[q*4+2], hi[q*4+3]);                \
            *(uint4*)(sb + A_LO_OFF + base + q*16) =                                 \
                make_uint4(lo[q*4], lo[q*4+1], lo[q*4+2], lo[q*4+3]);                \
            int4 p = fw[q];                                                          \
            *(uint4*)(sb + B_OFF + base + q*16) =                                    \
                make_uint4(dq(p.x), dq(p.y), dq(p.z), dq(p.w));                      \
        }                                                                            \
    } while (0)

    // ---- prologue ----
    LDG_TILE(0);
    STS_TILE(0);
    __syncthreads();
    LDG_TILE(1);

    for (int it = 0; it < NITER; ++it) {
        const uint32_t bufb = sbase + (uint32_t)(it & 1) * STAGE_BYTES;

        // compute current buffer: 4 k16 steps
        #pragma unroll
        for (int ks = 0; ks < 4; ks++) {
            uint32_t ah[4][4], al[4][4], bb[2][4];
            #pragma unroll
            for (int mt = 0; mt < 4; mt++) {
                uint32_t ad = bufb + A_HI_OFF + aRowOff + (uint32_t)mt * (16 * ROWB) + ks * 32;
                ldsm_x4(ah[mt][0], ah[mt][1], ah[mt][2], ah[mt][3], ad);
                uint32_t ad2 = bufb + A_LO_OFF + aRowOff + (uint32_t)mt * (16 * ROWB) + ks * 32;
                ldsm_x4(al[mt][0], al[mt][1], al[mt][2], al[mt][3], ad2);
            }
            #pragma unroll
            for (int nh = 0; nh < 2; nh++) {
                uint32_t bd = bufb + B_OFF + bRowOff + (uint32_t)nh * (16 * ROWB) + ks * 32;
                ldsm_x4(bb[nh][0], bb[nh][1], bb[nh][2], bb[nh][3], bd);
            }
            #pragma unroll
            for (int mt = 0; mt < 4; mt++) {
                #pragma unroll
                for (int nt = 0; nt < 4; nt++) {
                    const int nh = nt >> 1, p = nt & 1;
                    uint32_t b0 = bb[nh][p];        // k 0-7
                    uint32_t b1 = bb[nh][p + 2];    // k 8-15
                    mma_bf16(acc[mt][nt][0], acc[mt][nt][1], acc[mt][nt][2], acc[mt][nt][3],
                             ah[mt][0], ah[mt][1], ah[mt][2], ah[mt][3], b0, b1);
                    mma_bf16(acc[mt][nt][0], acc[mt][nt][1], acc[mt][nt][2], acc[mt][nt][3],
                             al[mt][0], al[mt][1], al[mt][2], al[mt][3], b0, b1);
                }
            }
        }

        if (it + 1 < NITER) {
            STS_TILE((it + 1) & 1);
            __syncthreads();
            if (it + 2 < NITER) LDG_TILE(it + 2);
        }
    }

    // ---- epilogue: scale * acc + bias ----
    const float* Ss = (const float*)(smem + OFF_SCALE);
    const float* Bs = (const float*)(smem + OFF_BIAS);
    const int g = lane >> 2;            // row group
    const int t = lane & 3;             // col pair

    #pragma unroll
    for (int mt = 0; mt < 4; mt++) {
        #pragma unroll
        for (int nt = 0; nt < 4; nt++) {
            const int col = nWarp + (nt >> 1) * 16 + (nt & 1) * 8 + t * 2;
            const float s0 = Ss[col], s1 = Ss[col + 1];
            const float b0 = Bs[col], b1 = Bs[col + 1];
            const int r0 = nBase + mWarp + mt * 16 + g;
            float2 v0, v1;
            v0.x = acc[mt][nt][0] * s0 + b0;
            v0.y = acc[mt][nt][1] * s1 + b1;
            v1.x = acc[mt][nt][2] * s0 + b0;
            v1.y = acc[mt][nt][3] * s1 + b1;
            *(float2*)(out + (size_t)r0 * OUT_DIM + oBase + col)       = v0;
            *(float2*)(out + (size_t)(r0 + 8) * OUT_DIM + oBase + col) = v1;
        }
    }

    #undef LDG_TILE
    #undef STS_TILE
}

extern "C" void kernel_launch(void* const* d_in, const int* in_sizes, int n_in,
                              void* d_out, int out_size)
{
    const float* x    = (const float*)d_in[0];
    const int*   wp   = (const int*)  d_in[1];
    const float* ws   = (const float*)d_in[2];
    const float* bias = (const float*)d_in[3];
    float*       out  = (float*)d_out;

    const int Nrows = in_sizes[0] / IN_DIM;   // 4096

    cudaFuncSetAttribute(qlinear_mma, cudaFuncAttributeMaxDynamicSharedMemorySize, SMEM_TOTAL);

    dim3 grid(OUT_DIM / BN, Nrows / BM);
    qlinear_mma<<<grid, NTHREADS, SMEM_TOTAL>>>(x, wp, ws, bias, out);
}